// round 1
// baseline (speedup 1.0000x reference)
#include <cuda_runtime.h>
#include <cuda_bf16.h>
#include <cstdint>
#include <cstring>

// ---------------------------------------------------------------------------
// CLOPLayer: out[b,c,j] = x[b,c,perm[j]] where perm is a fixed pseudo-random
// neighbor-swap permutation generated with JAX threefry2x32 (seed 42).
// Permutation is computed bit-exactly on the HOST (capture time), shipped to
// the device as a 28KB __grid_constant__ kernel parameter (no allocations,
// no memcpys), unpacked to a __device__ global, then a bandwidth-bound
// vectorized gather kernel applies it.
// ---------------------------------------------------------------------------

#define N_ELEM 7056      // 84*84
#define DIM    84
#define NVEC   (N_ELEM / 4)   // 1764
#define ROWS_PER_BLK 16

__device__ int g_perm[N_ELEM];

struct PermArg { int v[N_ELEM]; };

__global__ void clop_unpack_kernel(const __grid_constant__ PermArg p) {
    int t = blockIdx.x * blockDim.x + threadIdx.x;
    if (t < N_ELEM) g_perm[t] = p.v[t];
}

__global__ __launch_bounds__(256) void clop_gather_kernel(
    const float* __restrict__ x, float* __restrict__ out, int nrows)
{
    int j4 = blockIdx.x * blockDim.x + threadIdx.x;   // vec4 column index
    if (j4 >= NVEC) return;
    int r0 = blockIdx.y * ROWS_PER_BLK;

    const int4 p = reinterpret_cast<const int4*>(g_perm)[j4];

    #pragma unroll 4
    for (int r = 0; r < ROWS_PER_BLK; ++r) {
        int row = r0 + r;
        if (row >= nrows) break;
        const float* base = x + (size_t)row * N_ELEM;
        float4 o;
        o.x = __ldg(base + p.x);
        o.y = __ldg(base + p.y);
        o.z = __ldg(base + p.z);
        o.w = __ldg(base + p.w);
        reinterpret_cast<float4*>(out)[(size_t)row * NVEC + j4] = o;
    }
}

// ---------------------------------------------------------------------------
// Host-side bit-exact JAX RNG replication
// ---------------------------------------------------------------------------

static inline uint32_t rotl32(uint32_t v, int r) {
    return (v << r) | (v >> (32 - r));
}

// Threefry-2x32, 20 rounds (Random123 / JAX threefry2x32_p)
static inline void threefry2x32(uint32_t k0, uint32_t k1,
                                uint32_t& x0, uint32_t& x1)
{
    const uint32_t ks0 = k0;
    const uint32_t ks1 = k1;
    const uint32_t ks2 = k0 ^ k1 ^ 0x1BD11BDAu;
    const int ra[4] = {13, 15, 26, 6};
    const int rb[4] = {17, 29, 16, 24};

    x0 += ks0; x1 += ks1;
    for (int i = 0; i < 4; i++) { x0 += x1; x1 = rotl32(x1, ra[i]); x1 ^= x0; }
    x0 += ks1; x1 += ks2 + 1u;
    for (int i = 0; i < 4; i++) { x0 += x1; x1 = rotl32(x1, rb[i]); x1 ^= x0; }
    x0 += ks2; x1 += ks0 + 2u;
    for (int i = 0; i < 4; i++) { x0 += x1; x1 = rotl32(x1, ra[i]); x1 ^= x0; }
    x0 += ks0; x1 += ks1 + 3u;
    for (int i = 0; i < 4; i++) { x0 += x1; x1 = rotl32(x1, rb[i]); x1 ^= x0; }
    x0 += ks1; x1 += ks2 + 4u;
    for (int i = 0; i < 4; i++) { x0 += x1; x1 = rotl32(x1, ra[i]); x1 ^= x0; }
    x0 += ks2; x1 += ks0 + 5u;
}

// jax_threefry_partitionable=True (default since jax 0.4.30) 32-bit path:
// 64-bit counter i -> threefry2x32(key, (hi32(i), lo32(i))), output = v0 ^ v1.
static inline uint32_t jax_random_bits32(uint32_t k0, uint32_t k1, uint64_t i) {
    uint32_t x0 = (uint32_t)(i >> 32);
    uint32_t x1 = (uint32_t)(i & 0xFFFFFFFFu);
    threefry2x32(k0, k1, x0, x1);
    return x0 ^ x1;
}

static void compute_perm(int* perm) {
    const int n = N_ELEM;
    const int dim = DIM;
    const int steps = 2 * n - 1;   // 14111

    // probs computed as in reference: python doubles -> f32, then f32 cumsum
    float probs[5];
    probs[0] = (float)(1.0 - 0.9 / 2.0);   // 0.55f
    for (int q = 1; q < 5; q++) probs[q] = (float)(0.9 / 8.0);  // 0.1125f
    float pc[5];
    pc[0] = probs[0];
    for (int q = 1; q < 5; q++) pc[q] = pc[q - 1] + probs[q];

    const int offsets[5] = {0, 1, -1, dim, -dim};

    for (int t = 0; t < n; t++) perm[t] = t;

    // key = jax.random.key(42) -> threefry key (0, 42)
    const uint32_t k0 = 0u, k1 = 42u;

    for (int s = 0; s < steps; s++) {
        // iters[s] = abs(s - (n-1))
        int i = s - (n - 1);
        if (i < 0) i = -i;

        // uniform f32 in [0,1)
        uint32_t bits = jax_random_bits32(k0, k1, (uint64_t)s);
        uint32_t fb = (bits >> 9) | 0x3F800000u;
        float u;
        memcpy(&u, &fb, 4);
        u -= 1.0f;

        // r = p_cuml[-1] * (1 - u); ind = searchsorted_left(p_cuml, r)
        float rv = pc[4] * (1.0f - u);
        int ind = 0;
        while (ind < 5 && pc[ind] < rv) ind++;
        if (ind > 4) ind = 4;  // unreachable, safety

        int idx = i + offsets[ind];
        if (ind != 0 && idx > 0 && idx < n) {
            int a = perm[i];
            perm[i] = perm[idx];
            perm[idx] = a;
        }
    }
}

// ---------------------------------------------------------------------------

extern "C" void kernel_launch(void* const* d_in, const int* in_sizes, int n_in,
                              void* d_out, int out_size) {
    const float* x = (const float*)d_in[0];
    float* out = (float*)d_out;
    int total = in_sizes[0];
    int nrows = total / N_ELEM;    // 512*9 = 4608

    // recompute every call (deterministic, no caching); static = storage only
    static PermArg parg;
    compute_perm(parg.v);

    clop_unpack_kernel<<<(N_ELEM + 255) / 256, 256>>>(parg);

    dim3 grid((NVEC + 255) / 256, (nrows + ROWS_PER_BLK - 1) / ROWS_PER_BLK);
    clop_gather_kernel<<<grid, 256>>>(x, out, nrows);
}

// round 3
// speedup vs baseline: 1.0955x; 1.0955x over previous
#include <cuda_runtime.h>
#include <cuda_bf16.h>
#include <cstdint>
#include <cstring>

// ---------------------------------------------------------------------------
// CLOPLayer: out[b,c,j] = x[b,c,perm[j]], perm = fixed JAX threefry(42)
// neighbor-swap permutation (host-computed bit-exactly, shipped as 28KB
// __grid_constant__ param, unpacked to __device__ global).
// Gather kernel stages each row in SMEM: global reads AND writes perfectly
// coalesced float4/float sectors; the scatter happens in shared memory with
// stride-1 (conflict-free) LDS. Perm values live in registers per thread.
// ---------------------------------------------------------------------------

#define N_ELEM 7056            // 84*84
#define DIM    84
#define NVEC   (N_ELEM / 4)    // 1764
#define NTHR   512
#define COLS_PER_THR 14        // ceil(7056/512)
#define VECS_PER_THR 4         // ceil(1764/512)
#define ROWS_PER_BLK 4

__device__ int g_perm[N_ELEM];

struct PermArg { int v[N_ELEM]; };

__global__ void clop_unpack_kernel(const __grid_constant__ PermArg p) {
    int t = blockIdx.x * blockDim.x + threadIdx.x;
    if (t < N_ELEM) g_perm[t] = p.v[t];
}

__global__ __launch_bounds__(NTHR) void clop_gather_kernel(
    const float* __restrict__ x, float* __restrict__ out, int nrows)
{
    __shared__ float rowbuf[N_ELEM];
    const int t = threadIdx.x;
    const int r0 = blockIdx.x * ROWS_PER_BLK;

    // perm values for this thread's columns, kept in registers for all rows
    int pc[COLS_PER_THR];
    #pragma unroll
    for (int k = 0; k < COLS_PER_THR; ++k) {
        int col = t + k * NTHR;
        pc[k] = (col < N_ELEM) ? g_perm[col] : 0;
    }

    for (int r = 0; r < ROWS_PER_BLK; ++r) {
        int row = r0 + r;
        if (row >= nrows) break;
        const float4* src = reinterpret_cast<const float4*>(x + (size_t)row * N_ELEM);
        float* dst = out + (size_t)row * N_ELEM;

        if (r) __syncthreads();   // previous gather done before overwrite

        // coalesced streaming load of the whole row into smem
        #pragma unroll
        for (int k = 0; k < VECS_PER_THR; ++k) {
            int v = t + k * NTHR;
            if (v < NVEC) {
                float4 d = __ldcs(src + v);
                reinterpret_cast<float4*>(rowbuf)[v] = d;
            }
        }
        __syncthreads();

        // permuted read from smem (stride-1 across warp => conflict-free),
        // coalesced streaming scalar stores
        #pragma unroll
        for (int k = 0; k < COLS_PER_THR; ++k) {
            int col = t + k * NTHR;
            if (col < N_ELEM) {
                __stcs(dst + col, rowbuf[pc[k]]);
            }
        }
    }
}

// ---------------------------------------------------------------------------
// Host-side bit-exact JAX RNG replication (threefry2x32, partitionable path)
// ---------------------------------------------------------------------------

static inline uint32_t rotl32(uint32_t v, int r) {
    return (v << r) | (v >> (32 - r));
}

static inline void threefry2x32(uint32_t k0, uint32_t k1,
                                uint32_t& x0, uint32_t& x1)
{
    const uint32_t ks0 = k0;
    const uint32_t ks1 = k1;
    const uint32_t ks2 = k0 ^ k1 ^ 0x1BD11BDAu;
    const int ra[4] = {13, 15, 26, 6};
    const int rb[4] = {17, 29, 16, 24};

    x0 += ks0; x1 += ks1;
    for (int i = 0; i < 4; i++) { x0 += x1; x1 = rotl32(x1, ra[i]); x1 ^= x0; }
    x0 += ks1; x1 += ks2 + 1u;
    for (int i = 0; i < 4; i++) { x0 += x1; x1 = rotl32(x1, rb[i]); x1 ^= x0; }
    x0 += ks2; x1 += ks0 + 2u;
    for (int i = 0; i < 4; i++) { x0 += x1; x1 = rotl32(x1, ra[i]); x1 ^= x0; }
    x0 += ks0; x1 += ks1 + 3u;
    for (int i = 0; i < 4; i++) { x0 += x1; x1 = rotl32(x1, rb[i]); x1 ^= x0; }
    x0 += ks1; x1 += ks2 + 4u;
    for (int i = 0; i < 4; i++) { x0 += x1; x1 = rotl32(x1, ra[i]); x1 ^= x0; }
    x0 += ks2; x1 += ks0 + 5u;
}

static inline uint32_t jax_random_bits32(uint32_t k0, uint32_t k1, uint64_t i) {
    uint32_t x0 = (uint32_t)(i >> 32);
    uint32_t x1 = (uint32_t)(i & 0xFFFFFFFFu);
    threefry2x32(k0, k1, x0, x1);
    return x0 ^ x1;
}

static void compute_perm(int* perm) {
    const int n = N_ELEM;
    const int dim = DIM;
    const int steps = 2 * n - 1;   // 14111

    float probs[5];
    probs[0] = (float)(1.0 - 0.9 / 2.0);
    for (int q = 1; q < 5; q++) probs[q] = (float)(0.9 / 8.0);
    float pc[5];
    pc[0] = probs[0];
    for (int q = 1; q < 5; q++) pc[q] = pc[q - 1] + probs[q];

    const int offsets[5] = {0, 1, -1, dim, -dim};

    for (int t = 0; t < n; t++) perm[t] = t;

    const uint32_t k0 = 0u, k1 = 42u;   // jax.random.key(42)

    for (int s = 0; s < steps; s++) {
        int i = s - (n - 1);
        if (i < 0) i = -i;

        uint32_t bits = jax_random_bits32(k0, k1, (uint64_t)s);
        uint32_t fb = (bits >> 9) | 0x3F800000u;
        float u;
        memcpy(&u, &fb, 4);
        u -= 1.0f;

        float rv = pc[4] * (1.0f - u);
        int ind = 0;
        while (ind < 5 && pc[ind] < rv) ind++;
        if (ind > 4) ind = 4;

        int idx = i + offsets[ind];
        if (ind != 0 && idx > 0 && idx < n) {
            int a = perm[i];
            perm[i] = perm[idx];
            perm[idx] = a;
        }
    }
}

// ---------------------------------------------------------------------------

extern "C" void kernel_launch(void* const* d_in, const int* in_sizes, int n_in,
                              void* d_out, int out_size) {
    const float* x = (const float*)d_in[0];
    float* out = (float*)d_out;
    int total = in_sizes[0];
    int nrows = total / N_ELEM;    // 512*9 = 4608

    static PermArg parg;           // storage only; recomputed every call
    compute_perm(parg.v);

    clop_unpack_kernel<<<(N_ELEM + 255) / 256, 256>>>(parg);

    int nblk = (nrows + ROWS_PER_BLK - 1) / ROWS_PER_BLK;
    clop_gather_kernel<<<nblk, NTHR>>>(x, out, nrows);
}